// round 15
// baseline (speedup 1.0000x reference)
#include <cuda_runtime.h>
#include <cuda.h>
#include <cuda_fp16.h>
#include <cstdint>

// ---------------------------------------------------------------------------
// SynthesisBlock via mma.sync (HMMA), TMA bulk-tensor producers.
// R15 = persistent conv CTAs with DYNAMIC tile stealing (atomic counter,
// acquired one chunk early so next-tile TMA prefetch still overlaps the
// epilogue). R14's static split lost to load imbalance; this restores
// balance while keeping the cross-tile pipeline. Math identical to R8+.
// ---------------------------------------------------------------------------
#define B_SZ 16
#define H_SZ 64
#define W_SZ 64
#define CIN  256
#define N1   256
#define N2   512
#define WDIM 128
#define PW   66          // padded H/W
#define NPIX (B_SZ * PW * PW)
#define NCTA 304         // persistent grid: 2 CTAs/SM x 152 SMs

// ---- device scratch ----
__device__ float g_s1[B_SZ * CIN];
__device__ float g_s2[B_SZ * CIN];
__device__ float g_d1[B_SZ * N1];
__device__ float g_d2[B_SZ * N2];
__device__ float g_ksq1[CIN * N1];
__device__ float g_ksq2[CIN * N2];
__device__ int   g_ctr[2];               // dynamic tile counters (reset in prep1)
__device__ __half g_xp [NPIX * CIN];     // conv1 input, modulated by s1
__device__ __half g_x2p[NPIX * CIN];     // conv2 input (h * s2)
__device__ __half g_w1h[9 * N1 * CIN];   // [tap][n][ci]
__device__ __half g_w2h[9 * N2 * CIN];

// ---------------------------------------------------------------------------
// low-level helpers
// ---------------------------------------------------------------------------
__device__ __forceinline__ uint32_t smem_to_u32(const void* p) {
    uint32_t a;
    asm("{ .reg .u64 t; cvta.to.shared.u64 t, %1; cvt.u32.u64 %0, t; }" : "=r"(a) : "l"(p));
    return a;
}

#define MBARRIER_INIT(addr, count) \
    asm volatile("mbarrier.init.shared.b64 [%0], %1;" :: "r"((uint32_t)(addr)), "r"((uint32_t)(count)) : "memory")

#define MBARRIER_EXPECT_TX(addr, tx) \
    asm volatile("mbarrier.arrive.expect_tx.shared.b64 _, [%0], %1;" :: "r"((uint32_t)(addr)), "r"((uint32_t)(tx)) : "memory")

#define MBARRIER_ARRIVE(addr) \
    asm volatile("mbarrier.arrive.shared.b64 _, [%0];" :: "r"((uint32_t)(addr)) : "memory")

#define MBARRIER_WAIT_PARITY(mbar_smem_addr, phase_parity) do { \
    uint32_t _mbar = (uint32_t)(mbar_smem_addr); \
    uint32_t _parity = (uint32_t)(phase_parity); \
    uint32_t _done; \
    asm volatile( \
        "{\n\t.reg .pred p;\n\t" \
        "mbarrier.try_wait.parity.acquire.cta.shared::cta.b64 p, [%1], %2;\n\t" \
        "selp.b32 %0, 1, 0, p;\n\t}" \
        : "=r"(_done) : "r"(_mbar), "r"(_parity) : "memory"); \
    if (!_done) { \
        asm volatile( \
            "{\n\t.reg .pred P1;\n\t" \
            "WAIT_LOOP_%=:\n\t" \
            "mbarrier.try_wait.parity.acquire.cta.shared::cta.b64 P1, [%0], %1, 0x989680;\n\t" \
            "@P1 bra.uni WAIT_DONE_%=;\n\t" \
            "bra.uni WAIT_LOOP_%=;\n\t" \
            "WAIT_DONE_%=:\n\t}" \
            :: "r"(_mbar), "r"(_parity) : "memory"); \
    } \
} while(0)

// Relaxed wait: producer-side only (post-wait accesses are async-proxy TMA).
#define MBARRIER_WAIT_PARITY_RELAXED(mbar_smem_addr, phase_parity) do { \
    uint32_t _mbar = (uint32_t)(mbar_smem_addr); \
    uint32_t _parity = (uint32_t)(phase_parity); \
    uint32_t _done; \
    asm volatile( \
        "{\n\t.reg .pred p;\n\t" \
        "mbarrier.try_wait.parity.relaxed.cta.shared::cta.b64 p, [%1], %2, 0x989680;\n\t" \
        "selp.b32 %0, 1, 0, p;\n\t}" \
        : "=r"(_done) : "r"(_mbar), "r"(_parity) : "memory"); \
    if (!_done) { \
        asm volatile( \
            "{\n\t.reg .pred P1;\n\t" \
            "WAIT_LOOP_%=:\n\t" \
            "mbarrier.try_wait.parity.relaxed.cta.shared::cta.b64 P1, [%0], %1, 0x989680;\n\t" \
            "@P1 bra.uni WAIT_DONE_%=;\n\t" \
            "bra.uni WAIT_LOOP_%=;\n\t" \
            "WAIT_DONE_%=:\n\t}" \
            :: "r"(_mbar), "r"(_parity) : "memory"); \
    } \
} while(0)

#define TMA_LOAD_2D(smem_addr, tensor_map, cx, cy, mbar) \
    asm volatile( \
        "cp.async.bulk.tensor.2d.shared::cta.global.tile.mbarrier::complete_tx::bytes " \
        "[%0], [%1, {%2, %3}], [%4];" \
        :: "r"((uint32_t)(smem_addr)), "l"(tensor_map), \
           "r"((int32_t)(cx)), "r"((int32_t)(cy)), "r"((uint32_t)(mbar)) : "memory")

#define TMA_LOAD_3D(smem_addr, tensor_map, cx, cy, cz, mbar) \
    asm volatile( \
        "cp.async.bulk.tensor.3d.shared::cta.global.tile.mbarrier::complete_tx::bytes " \
        "[%0], [%1, {%2, %3, %4}], [%5];" \
        :: "r"((uint32_t)(smem_addr)), "l"(tensor_map), \
           "r"((int32_t)(cx)), "r"((int32_t)(cy)), "r"((int32_t)(cz)), \
           "r"((uint32_t)(mbar)) : "memory")

#define LDSM4(r, addr) \
    asm volatile("ldmatrix.sync.aligned.m8n8.x4.shared.b16 {%0,%1,%2,%3}, [%4];" \
        : "=r"((r)[0]), "=r"((r)[1]), "=r"((r)[2]), "=r"((r)[3]) : "r"(addr))

#define MMA16816(d, a, b0_, b1_) \
    asm volatile("mma.sync.aligned.m16n8k16.row.col.f32.f16.f16.f32 " \
        "{%0,%1,%2,%3}, {%4,%5,%6,%7}, {%8,%9}, {%0,%1,%2,%3};" \
        : "+f"((d)[0]), "+f"((d)[1]), "+f"((d)[2]), "+f"((d)[3]) \
        : "r"((a)[0]), "r"((a)[1]), "r"((a)[2]), "r"((a)[3]), "r"(b0_), "r"(b1_))

// ---------------------------------------------------------------------------
// prep kernel 1: style + ksq + wsplit (+ tile-counter reset)
// ---------------------------------------------------------------------------
#define NB_STYLE 32
#define NB_KSQ   768
#define NB_WSPL  1152
#define NB_PREP1 (NB_STYLE + NB_KSQ + NB_WSPL)

__global__ void prep1(const float* __restrict__ w,
                      const float* __restrict__ a1w, const float* __restrict__ a1b,
                      const float* __restrict__ a2w, const float* __restrict__ a2b,
                      const float* __restrict__ k1,  const float* __restrict__ k2)
{
    const int blk = blockIdx.x;
    const int tid = threadIdx.x;

    if (blk < NB_STYLE) {
        if (blk == 0 && tid == 0) { g_ctr[0] = NCTA; g_ctr[1] = NCTA; }
        const int b = blk >> 1, which = blk & 1;
        const float* aw = which ? a2w : a1w;
        const float* ab = which ? a2b : a1b;
        float sum = ab[tid];
        const float* wr = w + b * WDIM;
        #pragma unroll 8
        for (int k = 0; k < WDIM; ++k) sum += wr[k] * aw[k * CIN + tid];
        (which ? g_s2 : g_s1)[b * CIN + tid] = sum;
        return;
    }
    if (blk < NB_STYLE + NB_KSQ) {
        const int i    = blk - NB_STYLE;
        const int conv = (i >= 256);
        const int NT   = conv ? N2 : N1;
        const int total = CIN * NT;
        const int idx  = (conv ? i - 256 : i) * 256 + tid;
        const float* kern = conv ? k2 : k1;
        float s = 0.f;
        #pragma unroll
        for (int p = 0; p < 9; ++p) {
            float v = kern[(size_t)p * total + idx];
            s += v * v;
        }
        (conv ? g_ksq2 : g_ksq1)[idx] = s;
        return;
    }
    {
        const int i    = blk - NB_STYLE - NB_KSQ;
        const int ci_t = i & 7;
        const int rest = i >> 3;
        const int n_t  = rest & 7;
        const int z    = rest >> 3;
        const int conv = z / 9;
        const int tap  = z % 9;
        const int NT   = conv ? N2 : N1;
        if (n_t * 64 >= NT) return;
        const int ci0 = ci_t * 32;
        const int n0  = n_t * 64;
        const float* kern = conv ? k2 : k1;
        __half* dst = conv ? g_w2h : g_w1h;

        __shared__ __half tile[32][66];
        const int tx = tid & 63;
        const int ty = tid >> 6;
        #pragma unroll
        for (int q = 0; q < 8; ++q) {
            const int ci = q * 4 + ty;
            tile[ci][tx] = __float2half_rn(
                kern[((size_t)(tap * CIN + ci0 + ci)) * NT + n0 + tx]);
        }
        __syncthreads();

        const int cp = tid & 15;
        const int nn = tid >> 4;
        #pragma unroll
        for (int q = 0; q < 4; ++q) {
            const int n = q * 16 + nn;
            const __half2 hv = __halves2half2(tile[2 * cp][n], tile[2 * cp + 1][n]);
            *reinterpret_cast<__half2*>(
                dst + ((size_t)(tap * NT + n0 + n)) * CIN + ci0 + 2 * cp) = hv;
        }
    }
}

// ---------------------------------------------------------------------------
// prep kernel 2: demod + pad
// ---------------------------------------------------------------------------
#define NB_DEMOD 48
#define NB_PAD   (NPIX / 4)
#define NB_PREP2 (NB_DEMOD + NB_PAD)

__global__ void prep2(const float* __restrict__ x)
{
    const int blk = blockIdx.x;
    const int tid = threadIdx.x;

    if (blk < NB_DEMOD) {
        const int xb   = blk % 3;
        const int b    = blk / 3;
        const int conv = (xb >= 1);
        const int NT   = conv ? N2 : N1;
        const int co   = conv ? (xb - 1) * 256 + tid : tid;
        const float* st = conv ? g_s2 : g_s1;
        const float* kq = conv ? g_ksq2 : g_ksq1;

        __shared__ float ssq[CIN];
        ssq[tid] = st[b * CIN + tid] * st[b * CIN + tid];
        __syncthreads();

        float acc = 0.f;
        #pragma unroll 8
        for (int ci = 0; ci < CIN; ++ci)
            acc += ssq[ci] * kq[ci * NT + co];
        (conv ? g_d2 : g_d1)[b * NT + co] = rsqrtf(acc + 1e-8f);
        return;
    }
    {
        const int pix = (blk - NB_DEMOD) * 4 + (tid >> 6);
        const int ci  = (tid & 63) << 2;
        const int b  = pix / (PW * PW);
        const int r  = pix % (PW * PW);
        const int hp = r / PW, wp = r % PW;
        const bool interior = (hp >= 1) && (hp <= H_SZ) && (wp >= 1) && (wp <= W_SZ);

        uint2 packed = make_uint2(0u, 0u);
        if (interior) {
            const float4 v = *reinterpret_cast<const float4*>(
                x + (((size_t)b * H_SZ + (hp - 1)) * W_SZ + (wp - 1)) * CIN + ci);
            const float4 s = *reinterpret_cast<const float4*>(g_s1 + b * CIN + ci);
            __half2 p0 = __halves2half2(__float2half_rn(v.x * s.x), __float2half_rn(v.y * s.y));
            __half2 p1 = __halves2half2(__float2half_rn(v.z * s.z), __float2half_rn(v.w * s.w));
            packed.x = *reinterpret_cast<uint32_t*>(&p0);
            packed.y = *reinterpret_cast<uint32_t*>(&p1);
        }
        const size_t o = (size_t)pix * CIN + ci;
        *reinterpret_cast<uint2*>(g_xp + o) = packed;
        if (!interior)
            *reinterpret_cast<uint2*>(g_x2p + o) = make_uint2(0u, 0u);
    }
}

// ---------------------------------------------------------------------------
// conv GEMM, persistent + dynamic tile stealing. CTA tile: 128 px x 128 co,
// 256 thr, 8 warps (4m x 2n), warp tile 32x64, 2 CTAs/SM, NCTA CTAs.
// Tile 0 = blockIdx.x; subsequent tiles via atomicAdd(g_ctr[CONV]), acquired
// at the last chunk's first stage so next-tile A/W TMAs overlap the epilogue.
// Buffer parities depend only on per-CTA stage counts (gs/gc) - unchanged.
//   A: 264-row slab per ci-chunk (2 boxes of 136 rows), 2 buffers.
//   W: three taps per stage (box z=3), 2 buffers, lead-1.
// Barriers @ sb: AF0=0 AF1=8 WF0=16 WF1=24 AE0=40 AE1=48 WE0=56 WE1=64
// Next-tile broadcast: int at sb+80.
// ---------------------------------------------------------------------------
#define ROWB       80
#define A_BOX_H    136
#define A_BOX_B    (A_BOX_H * ROWB)       // 10880 = 85*128
#define A_PLANE_B  (2 * A_BOX_B)          // 21760
#define W_PLANE_B  (128 * ROWB)           // 10240 (one tap)
#define W_STG_B    (3 * W_PLANE_B)        // 30720 (three taps)
#define SM_CTRL    1024
#define SMEM_TOTAL (SM_CTRL + 2 * A_PLANE_B + 2 * W_STG_B)   // 105984

template<int CONV>
__global__ void __launch_bounds__(256, 2)
conv_mma(const __grid_constant__ CUtensorMap mA,
         const __grid_constant__ CUtensorMap mWh,
         const float* __restrict__ noise,
         const float* __restrict__ nscale,
         const float* __restrict__ bias,
         float* __restrict__ outp)
{
    constexpr int NTOT   = CONV ? N2 : N1;
    constexpr int NTILEN = NTOT / 128;            // 2 or 4
    constexpr int TOTAL  = NTILEN * 512;          // 1024 or 2048
    extern __shared__ __align__(128) char smem[];
    const uint32_t sb  = smem_to_u32(smem);
    const uint32_t sbD = sb + SM_CTRL;
    const uint32_t sbW = sbD + 2 * A_PLANE_B;

    const int tid  = threadIdx.x;
    const int lane = tid & 31;
    const int warp = tid >> 5;
    const int wm   = warp >> 1;          // 0..3  (32-row m slice)
    const int wn   = warp & 1;           // 0..1  (64-col n slice)

    if (tid == 0) {
        MBARRIER_INIT(sb + 0, 1);  MBARRIER_INIT(sb + 8, 1);    // A full
        MBARRIER_INIT(sb + 16, 1); MBARRIER_INIT(sb + 24, 1);   // W full
        MBARRIER_INIT(sb + 40, 8); MBARRIER_INIT(sb + 48, 8);   // A empty
        MBARRIER_INIT(sb + 56, 8); MBARRIER_INIT(sb + 64, 8);   // W empty
    }
    __syncthreads();

    // ---- ldmatrix fragment smem offsets (relative to buffer base) ----
    uint32_t a_base[2];
    #pragma unroll
    for (int mf = 0; mf < 2; ++mf) {
        const int m    = wm * 32 + mf * 16 + (lane & 15);
        const int srow = (m >> 6) * 66 + (m & 63);      // slab pixel-row (tap 0)
        a_base[mf] = (uint32_t)(srow * ROWB + ((lane >> 4) << 4));
    }
    uint32_t b_off[4];
    #pragma unroll
    for (int nf = 0; nf < 4; ++nf)
        b_off[nf] = (uint32_t)((wn * 64 + nf * 16 + (lane & 7) + ((lane >> 4) << 3)) * ROWB
                               + (((lane >> 3) & 1) << 4));

    int tile = blockIdx.x;               // NCTA <= TOTAL always

    // ---- prologue: A chunk 0 + W stage 0 (first tile) ----
    if (tid == 0) {
        const int mt = tile / NTILEN;
        const int pb = ((mt >> 5) * PW + ((mt & 31) << 1)) * PW;
        MBARRIER_EXPECT_TX(sb + 0, A_PLANE_B);
        TMA_LOAD_2D(sbD,           &mA, 0, pb,           sb + 0);
        TMA_LOAD_2D(sbD + A_BOX_B, &mA, 0, pb + A_BOX_H, sb + 0);
        MBARRIER_EXPECT_TX(sb + 16, W_STG_B);
        TMA_LOAD_3D(sbW, &mWh, 0, (tile % NTILEN) << 7, 0, sb + 16);
    }

    const float ns = nscale[0];
    const int q2 = (lane & 3) * 2;
    const int rr = lane >> 2;

    int gs = 0, gc = 0;
    int nextT = TOTAL;                   // tid0-private (valid after acquire)
    #pragma unroll 1
    while (true) {
        float acc[2][8][4];
        #pragma unroll
        for (int i = 0; i < 2; ++i)
            #pragma unroll
            for (int j = 0; j < 8; ++j)
                #pragma unroll
                for (int k = 0; k < 4; ++k) acc[i][j][k] = 0.f;

        #pragma unroll 1
        for (int c = 0; c < 8; ++c, ++gc) {
            const uint32_t Ab = sbD + (gc & 1) * A_PLANE_B;
            #pragma unroll 1
            for (int u = 0; u < 3; ++u, ++gs) {
                if (tid == 0) {
                    if (c == 7 && u == 0) {             // acquire next tile early
                        nextT = atomicAdd(&g_ctr[CONV], 1);
                        asm volatile("st.shared.b32 [%0], %1;" :: "r"(sb + 80), "r"(nextT) : "memory");
                    }
                    // W prefetch, lead-1 (crosses into next tile's stage 0)
                    const int sl = c * 3 + u;
                    int wTile = -1, wStage = 0;
                    if (sl + 1 < 24)          { wTile = tile;  wStage = sl + 1; }
                    else if (nextT < TOTAL)   { wTile = nextT; wStage = 0; }
                    if (wTile >= 0) {
                        const int ws = gs + 1;
                        const int wb = ws & 1;
                        if (ws >= 2)
                            MBARRIER_WAIT_PARITY_RELAXED(sb + 56 + wb * 8, ((ws >> 1) - 1) & 1);
                        MBARRIER_EXPECT_TX(sb + 16 + wb * 8, W_STG_B);
                        TMA_LOAD_3D(sbW + wb * W_STG_B, &mWh, (wStage / 3) * 32,
                                    (wTile % NTILEN) << 7, (wStage % 3) * 3, sb + 16 + wb * 8);
                    }
                    if (u == 0) {                       // A prefetch (next chunk / next tile)
                        int aTile = -1, aChunk = 0;
                        if (c < 7)               { aTile = tile;  aChunk = c + 1; }
                        else if (nextT < TOTAL)  { aTile = nextT; aChunk = 0; }
                        if (aTile >= 0) {
                            const int an = gc + 1;
                            const int ab = an & 1;
                            if (an >= 2)
                                MBARRIER_WAIT_PARITY_RELAXED(sb + 40 + ab * 8, ((an >> 1) - 1) & 1);
                            const uint32_t ab2 = sbD + ab * A_PLANE_B;
                            MBARRIER_EXPECT_TX(sb + ab * 8, A_PLANE_B);
                            const int mt2 = aTile / NTILEN;
                            const int pb  = ((mt2 >> 5) * PW + ((mt2 & 31) << 1)) * PW;
                            TMA_LOAD_2D(ab2,           &mA, aChunk * 32, pb,           sb + ab * 8);
                            TMA_LOAD_2D(ab2 + A_BOX_B, &mA, aChunk * 32, pb + A_BOX_H, sb + ab * 8);
                        }
                    }
                }
                if (u == 0)
                    MBARRIER_WAIT_PARITY(sb + (gc & 1) * 8, (gc >> 1) & 1);
                MBARRIER_WAIT_PARITY(sb + 16 + (gs & 1) * 8, (gs >> 1) & 1);

                // ---- compute taps 3u..3u+2 on chunk c ----
                const uint32_t Wb = sbW + (gs & 1) * W_STG_B;
                #pragma unroll
                for (int tt = 0; tt < 3; ++tt) {
                    const int t = u * 3 + tt;
                    const uint32_t Wtap = Wb + tt * W_PLANE_B;
                    const uint32_t Aofs = (uint32_t)(((t / 3) * 66 + (t % 3)) * ROWB);
                    #pragma unroll
                    for (int ks = 0; ks < 2; ++ks) {
                        uint32_t a0[4], a1r[4];
                        LDSM4(a0,  Ab + Aofs + a_base[0] + ks * 32);
                        LDSM4(a1r, Ab + Aofs + a_base[1] + ks * 32);
                        #pragma unroll
                        for (int nf = 0; nf < 4; ++nf) {
                            uint32_t bh[4];
                            LDSM4(bh, Wtap + b_off[nf] + ks * 32);
                            MMA16816(acc[0][nf * 2],     a0,  bh[0], bh[1]);
                            MMA16816(acc[0][nf * 2 + 1], a0,  bh[2], bh[3]);
                            MMA16816(acc[1][nf * 2],     a1r, bh[0], bh[1]);
                            MMA16816(acc[1][nf * 2 + 1], a1r, bh[2], bh[3]);
                        }
                    }
                }
                if (lane == 0) {
                    MBARRIER_ARRIVE(sb + 56 + (gs & 1) * 8);       // W consumed
                    if (u == 2)
                        MBARRIER_ARRIVE(sb + 40 + (gc & 1) * 8);   // A consumed
                }
            }
        }

        __syncthreads();                 // nextT broadcast visible to all
        int nt;
        asm volatile("ld.shared.b32 %0, [%1];" : "=r"(nt) : "r"(sb + 80) : "memory");

        // ---- epilogue for current tile (next tile's TMAs in flight) ----
        const int n0 = (tile % NTILEN) << 7;
        const int mt = tile / NTILEN;
        const int b  = mt >> 5;
        const int R  = (mt & 31) << 1;
        const float* __restrict__ dm = (CONV ? g_d2 : g_d1) + b * NTOT;

        #pragma unroll
        for (int mf = 0; mf < 2; ++mf) {
            #pragma unroll
            for (int hf = 0; hf < 2; ++hf) {
                const int ml = wm * 32 + mf * 16 + rr + hf * 8;    // 0..127
                const int h  = R + (ml >> 6);
                const int w  = ml & 63;
                const float nz = noise[((size_t)b * H_SZ + h) * W_SZ + w] * ns;
                #pragma unroll
                for (int nf = 0; nf < 8; ++nf) {
                    const int co = n0 + wn * 64 + nf * 8 + q2;
                    float v0 = acc[mf][nf][hf * 2]     * dm[co]     + nz + bias[co];
                    float v1 = acc[mf][nf][hf * 2 + 1] * dm[co + 1] + nz + bias[co + 1];
                    v0 = (v0 > 0.f) ? v0 : 0.2f * v0;
                    v1 = (v1 > 0.f) ? v1 : 0.2f * v1;
                    if (CONV == 0) {
                        const float m0 = v0 * g_s2[b * CIN + co];
                        const float m1 = v1 * g_s2[b * CIN + co + 1];
                        const size_t o = ((size_t)(b * PW + h + 1) * PW + (w + 1)) * CIN + co;
                        *reinterpret_cast<__half2*>(g_x2p + o) =
                            __halves2half2(__float2half_rn(m0), __float2half_rn(m1));
                    } else {
                        const int sh = co >> 8, sw = (co >> 7) & 1, c2 = co & 127;
                        float2 vv = make_float2(v0, v1);
                        *reinterpret_cast<float2*>(
                            outp + (((size_t)(b * 128 + 2 * h + sh)) * 128 + (2 * w + sw)) * 128 + c2) = vv;
                    }
                }
            }
        }

        tile = nt;
        if (tile >= TOTAL) break;
    }
}

// ---------------------------------------------------------------------------
// host
// ---------------------------------------------------------------------------
typedef CUresult (*PFN_tmap)(CUtensorMap*, CUtensorMapDataType, cuuint32_t, void*,
                             const cuuint64_t*, const cuuint64_t*, const cuuint32_t*,
                             const cuuint32_t*, CUtensorMapInterleave, CUtensorMapSwizzle,
                             CUtensorMapL2promotion, CUtensorMapFloatOOBfill);

static void encA(PFN_tmap fn, CUtensorMap* m, void* ptr)
{
    cuuint64_t dims[2]    = {CIN, NPIX};
    cuuint64_t strides[1] = {CIN * 2};
    cuuint32_t box[2]     = {40, A_BOX_H};
    cuuint32_t es[2]      = {1, 1};
    fn(m, CU_TENSOR_MAP_DATA_TYPE_FLOAT16, 2, ptr, dims, strides, box, es,
       CU_TENSOR_MAP_INTERLEAVE_NONE, CU_TENSOR_MAP_SWIZZLE_NONE,
       CU_TENSOR_MAP_L2_PROMOTION_L2_128B, CU_TENSOR_MAP_FLOAT_OOB_FILL_NONE);
}

static void encW(PFN_tmap fn, CUtensorMap* m, void* ptr, uint64_t ntot)
{
    cuuint64_t dims[3]    = {CIN, ntot, 9};
    cuuint64_t strides[2] = {CIN * 2, ntot * CIN * 2};
    cuuint32_t box[3]     = {40, 128, 3};
    cuuint32_t es[3]      = {1, 1, 1};
    fn(m, CU_TENSOR_MAP_DATA_TYPE_FLOAT16, 3, ptr, dims, strides, box, es,
       CU_TENSOR_MAP_INTERLEAVE_NONE, CU_TENSOR_MAP_SWIZZLE_NONE,
       CU_TENSOR_MAP_L2_PROMOTION_L2_128B, CU_TENSOR_MAP_FLOAT_OOB_FILL_NONE);
}

extern "C" void kernel_launch(void* const* d_in, const int* in_sizes, int n_in,
                              void* d_out, int out_size)
{
    const float* x    = (const float*)d_in[0];
    const float* w    = (const float*)d_in[1];
    const float* a1w  = (const float*)d_in[2];
    const float* a1b  = (const float*)d_in[3];
    const float* k1   = (const float*)d_in[4];
    const float* ns1  = (const float*)d_in[5];
    const float* b1   = (const float*)d_in[6];
    const float* a2w  = (const float*)d_in[7];
    const float* a2b  = (const float*)d_in[8];
    const float* k2   = (const float*)d_in[9];
    const float* ns2  = (const float*)d_in[10];
    const float* b2   = (const float*)d_in[11];
    const float* noi1 = (const float*)d_in[12];
    const float* noi2 = (const float*)d_in[13];
    float* outp = (float*)d_out;

    void* sym = nullptr;
    cudaDriverEntryPointQueryResult qres;
    cudaGetDriverEntryPoint("cuTensorMapEncodeTiled", &sym, cudaEnableDefault, &qres);
    PFN_tmap enc = (PFN_tmap)sym;

    void *pxp, *px2p, *pw1h, *pw2h;
    cudaGetSymbolAddress(&pxp,  g_xp);   cudaGetSymbolAddress(&px2p, g_x2p);
    cudaGetSymbolAddress(&pw1h, g_w1h);  cudaGetSymbolAddress(&pw2h, g_w2h);

    CUtensorMap mA1, mA2, mW1h, mW2h;
    encA(enc, &mA1, pxp);
    encA(enc, &mA2, px2p);
    encW(enc, &mW1h, pw1h, N1);
    encW(enc, &mW2h, pw2h, N2);

    cudaFuncSetAttribute(conv_mma<0>, cudaFuncAttributeMaxDynamicSharedMemorySize, SMEM_TOTAL);
    cudaFuncSetAttribute(conv_mma<1>, cudaFuncAttributeMaxDynamicSharedMemorySize, SMEM_TOTAL);

    // prep: 2 fused launches (prep1 also resets tile counters every replay)
    prep1<<<NB_PREP1, 256>>>(w, a1w, a1b, a2w, a2b, k1, k2);
    prep2<<<NB_PREP2, 256>>>(x);

    // conv1: xp -> x2p (epilogue multiplies by s2, single fp16 plane)
    conv_mma<0><<<NCTA, 256, SMEM_TOTAL>>>(mA1, mW1h, noi1, ns1, b1, nullptr);
    // conv2: x2p -> d_out (pixel shuffled)
    conv_mma<1><<<NCTA, 256, SMEM_TOTAL>>>(mA2, mW2h, noi2, ns2, b2, outp);
}

// round 17
// speedup vs baseline: 1.0272x; 1.0272x over previous
#include <cuda_runtime.h>
#include <cuda.h>
#include <cuda_fp16.h>
#include <cstdint>

// ---------------------------------------------------------------------------
// SynthesisBlock via mma.sync (HMMA), TMA bulk-tensor producers.
// R17 = R16 with the for-loop syntax error fixed. R13 conv structure
// (128x128 CTA, 3-tap W stages, 24 stages, mbarrier recycling) + epilogue
// operands staged in smem + pad writes interior only.
// ---------------------------------------------------------------------------
#define B_SZ 16
#define H_SZ 64
#define W_SZ 64
#define CIN  256
#define N1   256
#define N2   512
#define WDIM 128
#define PW   66          // padded H/W
#define NPIX (B_SZ * PW * PW)

// ---- device scratch (zero-initialized; pad/epilogue never write borders) ----
__device__ float g_s1[B_SZ * CIN];
__device__ float g_s2[B_SZ * CIN];
__device__ float g_d1[B_SZ * N1];
__device__ float g_d2[B_SZ * N2];
__device__ float g_ksq1[CIN * N1];
__device__ float g_ksq2[CIN * N2];
__device__ __half g_xp [NPIX * CIN];     // conv1 input, modulated by s1
__device__ __half g_x2p[NPIX * CIN];     // conv2 input (h * s2)
__device__ __half g_w1h[9 * N1 * CIN];   // [tap][n][ci]
__device__ __half g_w2h[9 * N2 * CIN];

// ---------------------------------------------------------------------------
// low-level helpers
// ---------------------------------------------------------------------------
__device__ __forceinline__ uint32_t smem_to_u32(const void* p) {
    uint32_t a;
    asm("{ .reg .u64 t; cvta.to.shared.u64 t, %1; cvt.u32.u64 %0, t; }" : "=r"(a) : "l"(p));
    return a;
}

#define MBARRIER_INIT(addr, count) \
    asm volatile("mbarrier.init.shared.b64 [%0], %1;" :: "r"((uint32_t)(addr)), "r"((uint32_t)(count)) : "memory")

#define MBARRIER_EXPECT_TX(addr, tx) \
    asm volatile("mbarrier.arrive.expect_tx.shared.b64 _, [%0], %1;" :: "r"((uint32_t)(addr)), "r"((uint32_t)(tx)) : "memory")

#define MBARRIER_ARRIVE(addr) \
    asm volatile("mbarrier.arrive.shared.b64 _, [%0];" :: "r"((uint32_t)(addr)) : "memory")

#define MBARRIER_WAIT_PARITY(mbar_smem_addr, phase_parity) do { \
    uint32_t _mbar = (uint32_t)(mbar_smem_addr); \
    uint32_t _parity = (uint32_t)(phase_parity); \
    uint32_t _done; \
    asm volatile( \
        "{\n\t.reg .pred p;\n\t" \
        "mbarrier.try_wait.parity.acquire.cta.shared::cta.b64 p, [%1], %2;\n\t" \
        "selp.b32 %0, 1, 0, p;\n\t}" \
        : "=r"(_done) : "r"(_mbar), "r"(_parity) : "memory"); \
    if (!_done) { \
        asm volatile( \
            "{\n\t.reg .pred P1;\n\t" \
            "WAIT_LOOP_%=:\n\t" \
            "mbarrier.try_wait.parity.acquire.cta.shared::cta.b64 P1, [%0], %1, 0x989680;\n\t" \
            "@P1 bra.uni WAIT_DONE_%=;\n\t" \
            "bra.uni WAIT_LOOP_%=;\n\t" \
            "WAIT_DONE_%=:\n\t}" \
            :: "r"(_mbar), "r"(_parity) : "memory"); \
    } \
} while(0)

// Relaxed wait: producer-side only (post-wait accesses are async-proxy TMA).
#define MBARRIER_WAIT_PARITY_RELAXED(mbar_smem_addr, phase_parity) do { \
    uint32_t _mbar = (uint32_t)(mbar_smem_addr); \
    uint32_t _parity = (uint32_t)(phase_parity); \
    uint32_t _done; \
    asm volatile( \
        "{\n\t.reg .pred p;\n\t" \
        "mbarrier.try_wait.parity.relaxed.cta.shared::cta.b64 p, [%1], %2, 0x989680;\n\t" \
        "selp.b32 %0, 1, 0, p;\n\t}" \
        : "=r"(_done) : "r"(_mbar), "r"(_parity) : "memory"); \
    if (!_done) { \
        asm volatile( \
            "{\n\t.reg .pred P1;\n\t" \
            "WAIT_LOOP_%=:\n\t" \
            "mbarrier.try_wait.parity.relaxed.cta.shared::cta.b64 P1, [%0], %1, 0x989680;\n\t" \
            "@P1 bra.uni WAIT_DONE_%=;\n\t" \
            "bra.uni WAIT_LOOP_%=;\n\t" \
            "WAIT_DONE_%=:\n\t}" \
            :: "r"(_mbar), "r"(_parity) : "memory"); \
    } \
} while(0)

#define TMA_LOAD_2D(smem_addr, tensor_map, cx, cy, mbar) \
    asm volatile( \
        "cp.async.bulk.tensor.2d.shared::cta.global.tile.mbarrier::complete_tx::bytes " \
        "[%0], [%1, {%2, %3}], [%4];" \
        :: "r"((uint32_t)(smem_addr)), "l"(tensor_map), \
           "r"((int32_t)(cx)), "r"((int32_t)(cy)), "r"((uint32_t)(mbar)) : "memory")

#define TMA_LOAD_3D(smem_addr, tensor_map, cx, cy, cz, mbar) \
    asm volatile( \
        "cp.async.bulk.tensor.3d.shared::cta.global.tile.mbarrier::complete_tx::bytes " \
        "[%0], [%1, {%2, %3, %4}], [%5];" \
        :: "r"((uint32_t)(smem_addr)), "l"(tensor_map), \
           "r"((int32_t)(cx)), "r"((int32_t)(cy)), "r"((int32_t)(cz)), \
           "r"((uint32_t)(mbar)) : "memory")

#define LDSM4(r, addr) \
    asm volatile("ldmatrix.sync.aligned.m8n8.x4.shared.b16 {%0,%1,%2,%3}, [%4];" \
        : "=r"((r)[0]), "=r"((r)[1]), "=r"((r)[2]), "=r"((r)[3]) : "r"(addr))

#define MMA16816(d, a, b0_, b1_) \
    asm volatile("mma.sync.aligned.m16n8k16.row.col.f32.f16.f16.f32 " \
        "{%0,%1,%2,%3}, {%4,%5,%6,%7}, {%8,%9}, {%0,%1,%2,%3};" \
        : "+f"((d)[0]), "+f"((d)[1]), "+f"((d)[2]), "+f"((d)[3]) \
        : "r"((a)[0]), "r"((a)[1]), "r"((a)[2]), "r"((a)[3]), "r"(b0_), "r"(b1_))

// ---------------------------------------------------------------------------
// prep kernel 1: style + ksq + wsplit (single launch, block-range dispatch)
// ---------------------------------------------------------------------------
#define NB_STYLE 32
#define NB_KSQ   768
#define NB_WSPL  1152
#define NB_PREP1 (NB_STYLE + NB_KSQ + NB_WSPL)

__global__ void prep1(const float* __restrict__ w,
                      const float* __restrict__ a1w, const float* __restrict__ a1b,
                      const float* __restrict__ a2w, const float* __restrict__ a2b,
                      const float* __restrict__ k1,  const float* __restrict__ k2)
{
    const int blk = blockIdx.x;
    const int tid = threadIdx.x;

    if (blk < NB_STYLE) {
        const int b = blk >> 1, which = blk & 1;
        const float* aw = which ? a2w : a1w;
        const float* ab = which ? a2b : a1b;
        float sum = ab[tid];
        const float* wr = w + b * WDIM;
        #pragma unroll 8
        for (int k = 0; k < WDIM; ++k) sum += wr[k] * aw[k * CIN + tid];
        (which ? g_s2 : g_s1)[b * CIN + tid] = sum;
        return;
    }
    if (blk < NB_STYLE + NB_KSQ) {
        const int i    = blk - NB_STYLE;
        const int conv = (i >= 256);
        const int NT   = conv ? N2 : N1;
        const int total = CIN * NT;
        const int idx  = (conv ? i - 256 : i) * 256 + tid;
        const float* kern = conv ? k2 : k1;
        float s = 0.f;
        #pragma unroll
        for (int p = 0; p < 9; ++p) {
            float v = kern[(size_t)p * total + idx];
            s += v * v;
        }
        (conv ? g_ksq2 : g_ksq1)[idx] = s;
        return;
    }
    {
        const int i    = blk - NB_STYLE - NB_KSQ;
        const int ci_t = i & 7;
        const int rest = i >> 3;
        const int n_t  = rest & 7;
        const int z    = rest >> 3;
        const int conv = z / 9;
        const int tap  = z % 9;
        const int NT   = conv ? N2 : N1;
        if (n_t * 64 >= NT) return;
        const int ci0 = ci_t * 32;
        const int n0  = n_t * 64;
        const float* kern = conv ? k2 : k1;
        __half* dst = conv ? g_w2h : g_w1h;

        __shared__ __half tile[32][66];
        const int tx = tid & 63;
        const int ty = tid >> 6;
        #pragma unroll
        for (int q = 0; q < 8; ++q) {
            const int ci = q * 4 + ty;
            tile[ci][tx] = __float2half_rn(
                kern[((size_t)(tap * CIN + ci0 + ci)) * NT + n0 + tx]);
        }
        __syncthreads();

        const int cp = tid & 15;
        const int nn = tid >> 4;
        #pragma unroll
        for (int q = 0; q < 4; ++q) {
            const int n = q * 16 + nn;
            const __half2 hv = __halves2half2(tile[2 * cp][n], tile[2 * cp + 1][n]);
            *reinterpret_cast<__half2*>(
                dst + ((size_t)(tap * NT + n0 + n)) * CIN + ci0 + 2 * cp) = hv;
        }
    }
}

// ---------------------------------------------------------------------------
// prep kernel 2: demod + pad (interior pixels only; padded borders of g_xp
// and g_x2p are never written by anyone -> stay zero-initialized)
// ---------------------------------------------------------------------------
#define NB_DEMOD 48
#define NB_PAD   (B_SZ * H_SZ * W_SZ / 4)      // 16384
#define NB_PREP2 (NB_DEMOD + NB_PAD)

__global__ void prep2(const float* __restrict__ x)
{
    const int blk = blockIdx.x;
    const int tid = threadIdx.x;

    if (blk < NB_DEMOD) {
        const int xb   = blk % 3;
        const int b    = blk / 3;
        const int conv = (xb >= 1);
        const int NT   = conv ? N2 : N1;
        const int co   = conv ? (xb - 1) * 256 + tid : tid;
        const float* st = conv ? g_s2 : g_s1;
        const float* kq = conv ? g_ksq2 : g_ksq1;

        __shared__ float ssq[CIN];
        ssq[tid] = st[b * CIN + tid] * st[b * CIN + tid];
        __syncthreads();

        float acc = 0.f;
        #pragma unroll 8
        for (int ci = 0; ci < CIN; ++ci)
            acc += ssq[ci] * kq[ci * NT + co];
        (conv ? g_d2 : g_d1)[b * NT + co] = rsqrtf(acc + 1e-8f);
        return;
    }
    {
        const int pixi = (blk - NB_DEMOD) * 4 + (tid >> 6);  // interior idx
        const int ci   = (tid & 63) << 2;
        const int b = pixi >> 12;
        const int r = pixi & 4095;
        const int h = r >> 6, w = r & 63;

        const float4 v = *reinterpret_cast<const float4*>(x + (size_t)pixi * CIN + ci);
        const float4 s = *reinterpret_cast<const float4*>(g_s1 + b * CIN + ci);
        __half2 p0 = __halves2half2(__float2half_rn(v.x * s.x), __float2half_rn(v.y * s.y));
        __half2 p1 = __halves2half2(__float2half_rn(v.z * s.z), __float2half_rn(v.w * s.w));
        uint2 packed;
        packed.x = *reinterpret_cast<uint32_t*>(&p0);
        packed.y = *reinterpret_cast<uint32_t*>(&p1);

        const size_t o = ((size_t)(b * PW + h + 1) * PW + (w + 1)) * CIN + ci;
        *reinterpret_cast<uint2*>(g_xp + o) = packed;
    }
}

// ---------------------------------------------------------------------------
// conv GEMM (R13 structure). CTA: 128 px x 128 co. 256 thr, 8 warps
// (4m x 2n), warp tile 32x64, 2 CTAs/SM. Per-warp mbarrier recycling.
//   A: 264-row slab per ci-chunk (2 boxes of 136 rows), 2 buffers.
//   W: THREE taps per stage (box z=3; 9 taps = 3 stages/chunk), 2 buffers,
//      lead-1 prefetch. 24 stages (8 chunks x 3).
// Epilogue operands (demod/bias/noise*ns/s2) staged into smem at tile start.
// Barriers @ sb: AF0=0 AF1=8 WF0=16 WF1=24 AE0=40 AE1=48 WE0=56 WE1=64
// Epilogue smem: eDM @ +256, eBI @ +768, eNZ @ +1280, eS2 @ +1792 (512B each)
// ---------------------------------------------------------------------------
#define ROWB       80
#define A_BOX_H    136
#define A_BOX_B    (A_BOX_H * ROWB)       // 10880 = 85*128
#define A_PLANE_B  (2 * A_BOX_B)          // 21760
#define W_PLANE_B  (128 * ROWB)           // 10240 (one tap)
#define W_STG_B    (3 * W_PLANE_B)        // 30720 (three taps)
#define SM_CTRL    2304
#define SMEM_TOTAL (SM_CTRL + 2 * A_PLANE_B + 2 * W_STG_B)   // 107264

template<int CONV>
__global__ void __launch_bounds__(256, 2)
conv_mma(const __grid_constant__ CUtensorMap mA,
         const __grid_constant__ CUtensorMap mWh,
         const float* __restrict__ noise,
         const float* __restrict__ nscale,
         const float* __restrict__ bias,
         float* __restrict__ outp)
{
    constexpr int NTOT = CONV ? N2 : N1;
    extern __shared__ __align__(128) char smem[];
    const uint32_t sb  = smem_to_u32(smem);
    const uint32_t sbD = sb + SM_CTRL;
    const uint32_t sbW = sbD + 2 * A_PLANE_B;
    float* eDM = reinterpret_cast<float*>(smem + 256);
    float* eBI = reinterpret_cast<float*>(smem + 768);
    float* eNZ = reinterpret_cast<float*>(smem + 1280);
    float* eS2 = reinterpret_cast<float*>(smem + 1792);

    const int tid  = threadIdx.x;
    const int lane = tid & 31;
    const int warp = tid >> 5;
    const int wm   = warp >> 1;          // 0..3  (32-row m slice)
    const int wn   = warp & 1;           // 0..1  (64-col n slice)

    const int mtile = blockIdx.y;        // 0..511
    const int b  = mtile >> 5;
    const int R  = (mtile & 31) << 1;    // first output image row
    const int n0 = blockIdx.x << 7;
    const int pixBase = (b * PW + R) * PW;

    if (tid == 0) {
        MBARRIER_INIT(sb + 0, 1);  MBARRIER_INIT(sb + 8, 1);    // A full
        MBARRIER_INIT(sb + 16, 1); MBARRIER_INIT(sb + 24, 1);   // W full
        MBARRIER_INIT(sb + 40, 8); MBARRIER_INIT(sb + 48, 8);   // A empty (8 warps)
        MBARRIER_INIT(sb + 56, 8); MBARRIER_INIT(sb + 64, 8);   // W empty
    }
    __syncthreads();

    // ---- prologue TMA: A chunk 0 + W stage 0 ----
    if (tid == 0) {
        MBARRIER_EXPECT_TX(sb + 0, A_PLANE_B);
        TMA_LOAD_2D(sbD,           &mA, 0, pixBase,           sb + 0);
        TMA_LOAD_2D(sbD + A_BOX_B, &mA, 0, pixBase + A_BOX_H, sb + 0);
        MBARRIER_EXPECT_TX(sb + 16, W_STG_B);
        TMA_LOAD_3D(sbW, &mWh, 0, n0, 0, sb + 16);
    }

    // ---- stage epilogue operands into smem (overlaps TMA prologue) ----
    if (tid < 128) {
        const float ns = nscale[0];
        eDM[tid] = (CONV ? g_d2 : g_d1)[b * NTOT + n0 + tid];
        eBI[tid] = bias[n0 + tid];
        const int h = R + (tid >> 6), w = tid & 63;
        eNZ[tid] = noise[((size_t)b * H_SZ + h) * W_SZ + w] * ns;
        if (CONV == 0) eS2[tid] = g_s2[b * CIN + n0 + tid];
    }

    // ---- ldmatrix fragment smem offsets (relative to buffer base) ----
    uint32_t a_base[2];
    #pragma unroll
    for (int mf = 0; mf < 2; ++mf) {
        const int m    = wm * 32 + mf * 16 + (lane & 15);
        const int srow = (m >> 6) * 66 + (m & 63);      // slab pixel-row (tap 0)
        a_base[mf] = (uint32_t)(srow * ROWB + ((lane >> 4) << 4));
    }
    uint32_t b_off[4];
    #pragma unroll
    for (int nf = 0; nf < 4; ++nf)
        b_off[nf] = (uint32_t)((wn * 64 + nf * 16 + (lane & 7) + ((lane >> 4) << 3)) * ROWB
                               + (((lane >> 3) & 1) << 4));

    float acc[2][8][4];
    #pragma unroll
    for (int i = 0; i < 2; ++i)
        #pragma unroll
        for (int j = 0; j < 8; ++j)
            #pragma unroll
            for (int k = 0; k < 4; ++k) acc[i][j][k] = 0.f;

    // ---- main loop: 8 chunks x 3 triple-tap stages; s = c*3 + u ----
    int s = 0;
    #pragma unroll 1
    for (int c = 0; c < 8; ++c) {
        const uint32_t Ab = sbD + (c & 1) * A_PLANE_B;
        #pragma unroll 1
        for (int u = 0; u < 3; ++u, ++s) {
            if (tid == 0) {
                const int ws = s + 1;                   // W prefetch, lead-1
                if (ws < 24) {
                    const int wb = ws & 1;
                    if (ws >= 2)
                        MBARRIER_WAIT_PARITY_RELAXED(sb + 56 + wb * 8, ((ws >> 1) - 1) & 1);
                    MBARRIER_EXPECT_TX(sb + 16 + wb * 8, W_STG_B);
                    TMA_LOAD_3D(sbW + wb * W_STG_B, &mWh, (ws / 3) * 32, n0,
                                (ws % 3) * 3, sb + 16 + wb * 8);
                }
                if (u == 0 && c < 7) {                  // A prefetch, chunk c+1
                    const int nc = c + 1;
                    const int ab = nc & 1;
                    if (nc >= 2)
                        MBARRIER_WAIT_PARITY_RELAXED(sb + 40 + ab * 8, ((nc >> 1) - 1) & 1);
                    const uint32_t ab2 = sbD + ab * A_PLANE_B;
                    MBARRIER_EXPECT_TX(sb + ab * 8, A_PLANE_B);
                    TMA_LOAD_2D(ab2,           &mA, nc * 32, pixBase,           sb + ab * 8);
                    TMA_LOAD_2D(ab2 + A_BOX_B, &mA, nc * 32, pixBase + A_BOX_H, sb + ab * 8);
                }
            }
            if (u == 0)
                MBARRIER_WAIT_PARITY(sb + (c & 1) * 8, (c >> 1) & 1);
            MBARRIER_WAIT_PARITY(sb + 16 + (s & 1) * 8, (s >> 1) & 1);

            // ---- compute taps 3u, 3u+1, 3u+2 on chunk c ----
            const uint32_t Wb = sbW + (s & 1) * W_STG_B;
            #pragma unroll
            for (int tt = 0; tt < 3; ++tt) {
                const int t = u * 3 + tt;
                const uint32_t Wtap = Wb + tt * W_PLANE_B;
                const uint32_t Aofs = (uint32_t)(((t / 3) * 66 + (t % 3)) * ROWB);
                #pragma unroll
                for (int ks = 0; ks < 2; ++ks) {
                    uint32_t a0[4], a1r[4];
                    LDSM4(a0,  Ab + Aofs + a_base[0] + ks * 32);
                    LDSM4(a1r, Ab + Aofs + a_base[1] + ks * 32);
                    #pragma unroll
                    for (int nf = 0; nf < 4; ++nf) {
                        uint32_t bh[4];
                        LDSM4(bh, Wtap + b_off[nf] + ks * 32);
                        MMA16816(acc[0][nf * 2],     a0,  bh[0], bh[1]);
                        MMA16816(acc[0][nf * 2 + 1], a0,  bh[2], bh[3]);
                        MMA16816(acc[1][nf * 2],     a1r, bh[0], bh[1]);
                        MMA16816(acc[1][nf * 2 + 1], a1r, bh[2], bh[3]);
                    }
                }
            }
            if (lane == 0) {
                MBARRIER_ARRIVE(sb + 56 + (s & 1) * 8);        // W stage consumed
                if (u == 2)
                    MBARRIER_ARRIVE(sb + 40 + (c & 1) * 8);    // A chunk consumed
            }
        }
    }

    __syncthreads();    // epilogue-operand smem visible to all warps

    // ---- epilogue (all operands from smem) ----
    const int q2 = (lane & 3) * 2;
    const int rr = lane >> 2;

    #pragma unroll
    for (int mf = 0; mf < 2; ++mf) {
        #pragma unroll
        for (int hf = 0; hf < 2; ++hf) {
            const int ml = wm * 32 + mf * 16 + rr + hf * 8;    // 0..127
            const int h  = R + (ml >> 6);
            const int w  = ml & 63;
            const float nz = eNZ[ml];
            #pragma unroll
            for (int nf = 0; nf < 8; ++nf) {
                const int cl = wn * 64 + nf * 8 + q2;          // 0..127 local co
                const int co = n0 + cl;
                float v0 = acc[mf][nf][hf * 2]     * eDM[cl]     + nz + eBI[cl];
                float v1 = acc[mf][nf][hf * 2 + 1] * eDM[cl + 1] + nz + eBI[cl + 1];
                v0 = (v0 > 0.f) ? v0 : 0.2f * v0;
                v1 = (v1 > 0.f) ? v1 : 0.2f * v1;
                if (CONV == 0) {
                    const float m0 = v0 * eS2[cl];
                    const float m1 = v1 * eS2[cl + 1];
                    const size_t o = ((size_t)(b * PW + h + 1) * PW + (w + 1)) * CIN + co;
                    *reinterpret_cast<__half2*>(g_x2p + o) =
                        __halves2half2(__float2half_rn(m0), __float2half_rn(m1));
                } else {
                    const int sh = co >> 8, sw = (co >> 7) & 1, c2 = co & 127;
                    float2 vv = make_float2(v0, v1);
                    *reinterpret_cast<float2*>(
                        outp + (((size_t)(b * 128 + 2 * h + sh)) * 128 + (2 * w + sw)) * 128 + c2) = vv;
                }
            }
        }
    }
}

// ---------------------------------------------------------------------------
// host
// ---------------------------------------------------------------------------
typedef CUresult (*PFN_tmap)(CUtensorMap*, CUtensorMapDataType, cuuint32_t, void*,
                             const cuuint64_t*, const cuuint64_t*, const cuuint32_t*,
                             const cuuint32_t*, CUtensorMapInterleave, CUtensorMapSwizzle,
                             CUtensorMapL2promotion, CUtensorMapFloatOOBfill);

static void encA(PFN_tmap fn, CUtensorMap* m, void* ptr)
{
    cuuint64_t dims[2]    = {CIN, NPIX};
    cuuint64_t strides[1] = {CIN * 2};
    cuuint32_t box[2]     = {40, A_BOX_H};
    cuuint32_t es[2]      = {1, 1};
    fn(m, CU_TENSOR_MAP_DATA_TYPE_FLOAT16, 2, ptr, dims, strides, box, es,
       CU_TENSOR_MAP_INTERLEAVE_NONE, CU_TENSOR_MAP_SWIZZLE_NONE,
       CU_TENSOR_MAP_L2_PROMOTION_L2_128B, CU_TENSOR_MAP_FLOAT_OOB_FILL_NONE);
}

static void encW(PFN_tmap fn, CUtensorMap* m, void* ptr, uint64_t ntot)
{
    cuuint64_t dims[3]    = {CIN, ntot, 9};
    cuuint64_t strides[2] = {CIN * 2, ntot * CIN * 2};
    cuuint32_t box[3]     = {40, 128, 3};
    cuuint32_t es[3]      = {1, 1, 1};
    fn(m, CU_TENSOR_MAP_DATA_TYPE_FLOAT16, 3, ptr, dims, strides, box, es,
       CU_TENSOR_MAP_INTERLEAVE_NONE, CU_TENSOR_MAP_SWIZZLE_NONE,
       CU_TENSOR_MAP_L2_PROMOTION_L2_128B, CU_TENSOR_MAP_FLOAT_OOB_FILL_NONE);
}

extern "C" void kernel_launch(void* const* d_in, const int* in_sizes, int n_in,
                              void* d_out, int out_size)
{
    const float* x    = (const float*)d_in[0];
    const float* w    = (const float*)d_in[1];
    const float* a1w  = (const float*)d_in[2];
    const float* a1b  = (const float*)d_in[3];
    const float* k1   = (const float*)d_in[4];
    const float* ns1  = (const float*)d_in[5];
    const float* b1   = (const float*)d_in[6];
    const float* a2w  = (const float*)d_in[7];
    const float* a2b  = (const float*)d_in[8];
    const float* k2   = (const float*)d_in[9];
    const float* ns2  = (const float*)d_in[10];
    const float* b2   = (const float*)d_in[11];
    const float* noi1 = (const float*)d_in[12];
    const float* noi2 = (const float*)d_in[13];
    float* outp = (float*)d_out;

    void* sym = nullptr;
    cudaDriverEntryPointQueryResult qres;
    cudaGetDriverEntryPoint("cuTensorMapEncodeTiled", &sym, cudaEnableDefault, &qres);
    PFN_tmap enc = (PFN_tmap)sym;

    void *pxp, *px2p, *pw1h, *pw2h;
    cudaGetSymbolAddress(&pxp,  g_xp);   cudaGetSymbolAddress(&px2p, g_x2p);
    cudaGetSymbolAddress(&pw1h, g_w1h);  cudaGetSymbolAddress(&pw2h, g_w2h);

    CUtensorMap mA1, mA2, mW1h, mW2h;
    encA(enc, &mA1, pxp);
    encA(enc, &mA2, px2p);
    encW(enc, &mW1h, pw1h, N1);
    encW(enc, &mW2h, pw2h, N2);

    cudaFuncSetAttribute(conv_mma<0>, cudaFuncAttributeMaxDynamicSharedMemorySize, SMEM_TOTAL);
    cudaFuncSetAttribute(conv_mma<1>, cudaFuncAttributeMaxDynamicSharedMemorySize, SMEM_TOTAL);

    // prep: 2 fused launches
    prep1<<<NB_PREP1, 256>>>(w, a1w, a1b, a2w, a2b, k1, k2);
    prep2<<<NB_PREP2, 256>>>(x);

    // conv1: xp -> x2p (epilogue multiplies by s2, single fp16 plane)
    {
        dim3 grid(N1 / 128, 512);
        conv_mma<0><<<grid, 256, SMEM_TOTAL>>>(mA1, mW1h, noi1, ns1, b1, nullptr);
    }
    // conv2: x2p -> d_out (pixel shuffled)
    {
        dim3 grid(N2 / 128, 512);
        conv_mma<1><<<grid, 256, SMEM_TOTAL>>>(mA2, mW2h, noi2, ns2, b2, outp);
    }
}